// round 3
// baseline (speedup 1.0000x reference)
#include <cuda_runtime.h>
#include <math.h>

#define NB 2
#define NS 2048
#define ND 768
#define NH 12
#define NHD 64
#define NQKV 2304
#define NROWS 4096   // NB*NS

#define NEG_BIG (-1e30f)
#define PAD 68

typedef unsigned long long ull;

// ---- packed f32x2 helpers (FFMA2 path, PTX-only per SASS_QUICKREF) ----
__device__ __forceinline__ ull f2_dup(float x) {
    ull r; asm("mov.b64 %0, {%1, %1};" : "=l"(r) : "f"(x)); return r;
}
__device__ __forceinline__ void f2_fma(ull& d, ull a, ull b) {
    asm("fma.rn.f32x2 %0, %1, %2, %0;" : "+l"(d) : "l"(a), "l"(b));
}
__device__ __forceinline__ ull f2_mul(ull a, ull b) {
    ull r; asm("mul.rn.f32x2 %0, %1, %2;" : "=l"(r) : "l"(a), "l"(b)); return r;
}
__device__ __forceinline__ void f2_unpack(ull v, float& lo, float& hi) {
    asm("mov.b64 {%0, %1}, %2;" : "=f"(lo), "=f"(hi) : "l"(v));
}

// Scratch (device globals: allocation-free per harness rules)
__device__ float g_qkv[(size_t)NROWS * NQKV];   // 37.7 MB
__device__ float g_attn[(size_t)NROWS * ND];    // 12.6 MB

// ---------------------------------------------------------------------------
// SGEMM + bias: C[M,N] = A[M,K] @ W[K,N] + bias[N]
// 128x128 tile, BK=16, 256 threads, 8x8 per-thread tile computed as
// 4 row-pairs x 8 cols in packed f32x2 (FFMA2).
// ---------------------------------------------------------------------------
__global__ __launch_bounds__(256, 2)
void sgemm_bias_kernel(const float* __restrict__ A, const float* __restrict__ W,
                       const float* __restrict__ bias, float* __restrict__ C,
                       int M, int N, int K)
{
    __shared__ float As[16 * 132];   // stored transposed: As[k][row]
    __shared__ float Bs[16 * 132];   // Bs[k][col]
    const int tid  = threadIdx.x;
    const int row0 = blockIdx.y * 128;
    const int col0 = blockIdx.x * 128;
    const int tr   = (tid >> 4) * 8;
    const int tc   = (tid & 15) * 8;

    ull acc2[4][8];   // [row-pair][col]; lo lane = row tr+2*i2, hi = tr+2*i2+1
#pragma unroll
    for (int i = 0; i < 4; i++)
#pragma unroll
        for (int j = 0; j < 8; j++) acc2[i][j] = 0ull;

    for (int k0 = 0; k0 < K; k0 += 16) {
#pragma unroll
        for (int l = 0; l < 2; l++) {
            int f  = tid + l * 256;
            int ar = f >> 2;
            int ac = (f & 3) * 4;
            float4 a4 = *(const float4*)(A + (size_t)(row0 + ar) * K + k0 + ac);
            As[(ac + 0) * 132 + ar] = a4.x;
            As[(ac + 1) * 132 + ar] = a4.y;
            As[(ac + 2) * 132 + ar] = a4.z;
            As[(ac + 3) * 132 + ar] = a4.w;
            int br = f >> 5;
            int bc = (f & 31) * 4;
            *(float4*)&Bs[br * 132 + bc] =
                *(const float4*)(W + (size_t)(k0 + br) * N + col0 + bc);
        }
        __syncthreads();
#pragma unroll
        for (int kk = 0; kk < 16; kk++) {
            ull a2[4];
            a2[0] = *(const ull*)&As[kk * 132 + tr + 0];
            a2[1] = *(const ull*)&As[kk * 132 + tr + 2];
            a2[2] = *(const ull*)&As[kk * 132 + tr + 4];
            a2[3] = *(const ull*)&As[kk * 132 + tr + 6];
            float b[8];
            *(float4*)&b[0] = *(const float4*)&Bs[kk * 132 + tc];
            *(float4*)&b[4] = *(const float4*)&Bs[kk * 132 + tc + 4];
#pragma unroll
            for (int j = 0; j < 8; j++) {
                ull bd = f2_dup(b[j]);
#pragma unroll
                for (int i = 0; i < 4; i++)
                    f2_fma(acc2[i][j], a2[i], bd);
            }
        }
        __syncthreads();
    }

    float bv[8];
    *(float4*)&bv[0] = *(const float4*)(bias + col0 + tc);
    *(float4*)&bv[4] = *(const float4*)(bias + col0 + tc + 4);
#pragma unroll
    for (int i2 = 0; i2 < 4; i2++) {
        float r0[8], r1[8];
#pragma unroll
        for (int j = 0; j < 8; j++) {
            float lo, hi;
            f2_unpack(acc2[i2][j], lo, hi);
            r0[j] = lo + bv[j];
            r1[j] = hi + bv[j];
        }
        float* cp0 = C + (size_t)(row0 + tr + 2 * i2) * N + col0 + tc;
        float* cp1 = cp0 + N;
        *(float4*)cp0       = *(float4*)&r0[0];
        *(float4*)(cp0 + 4) = *(float4*)&r0[4];
        *(float4*)cp1       = *(float4*)&r1[0];
        *(float4*)(cp1 + 4) = *(float4*)&r1[4];
    }
}

// ---------------------------------------------------------------------------
// RoPE in-place on q and k parts of qkv. One thread per (b,s,h,pair).
// ---------------------------------------------------------------------------
__global__ void rope_kernel(float* __restrict__ qkv, const int* __restrict__ layer_p)
{
    int idx = blockIdx.x * blockDim.x + threadIdx.x;
    if (idx >= NROWS * NH * 32) return;
    int i  = idx & 31;          // rotation pair index
    int hh = (idx >> 5) % NH;
    int bs = (idx >> 5) / NH;   // b*NS + s
    int s  = bs & (NS - 1);

    bool is_global = (layer_p[0] % 3) == 0;
    float theta = is_global ? 160000.f : 10000.f;
    float freq  = powf(theta, -(float)(2 * i) / 64.f);
    float ang   = (float)s * freq;
    float sn, cs;
    sincosf(ang, &sn, &cs);

    size_t base = (size_t)bs * NQKV + hh * NHD + 2 * i;
    float qe = qkv[base], qo = qkv[base + 1];
    qkv[base]      = qe * cs - qo * sn;
    qkv[base + 1]  = qo * cs + qe * sn;
    float ke = qkv[base + ND], ko = qkv[base + ND + 1];
    qkv[base + ND]     = ke * cs - ko * sn;
    qkv[base + ND + 1] = ko * cs + ke * sn;
}

// ---------------------------------------------------------------------------
// Flash-style banded attention. One block per (b, h, 64-row query tile).
// Local layer: key tiles qt-2..qt+2 (band |i-j|<=128). Global: all tiles.
// Matmul loops use packed f32x2 FFMA2.
// ---------------------------------------------------------------------------
__global__ __launch_bounds__(256, 1)
void attn_kernel(const float* __restrict__ qkv, float* __restrict__ aout,
                 const int* __restrict__ layer_p)
{
    extern __shared__ float sm[];
    float* Qt    = sm;               // [64][PAD] Qt[d*PAD+r] (pre-scaled)
    float* Ks    = Qt + 64 * PAD;    // K transposed [d][r]; reused as P[r][c]
    float* Vs    = Ks + 64 * PAD;    // V row-major [key][dim]
    float* row_m = Vs + 64 * PAD;
    float* row_l = row_m + 64;
    float* row_s = row_l + 64;

    const int tid = threadIdx.x;
    const int blk = blockIdx.x;
    const int qt  = blk & 31;
    const int hh  = (blk >> 5) % NH;
    const int b   = blk / (32 * NH);
    const bool is_global = (layer_p[0] % 3) == 0;
    const int q0 = qt * 64;

    // Load Q tile (scaled by 1/sqrt(64)) transposed
    {
        int r = tid >> 2;
        int part = tid & 3;
        const float* src = qkv + (size_t)(b * NS + q0 + r) * NQKV + hh * NHD + part * 16;
#pragma unroll
        for (int v = 0; v < 4; v++) {
            float4 q4 = *(const float4*)(src + v * 4);
            int d0 = part * 16 + v * 4;
            Qt[(d0 + 0) * PAD + r] = q4.x * 0.125f;
            Qt[(d0 + 1) * PAD + r] = q4.y * 0.125f;
            Qt[(d0 + 2) * PAD + r] = q4.z * 0.125f;
            Qt[(d0 + 3) * PAD + r] = q4.w * 0.125f;
        }
    }
    if (tid < 64) { row_m[tid] = NEG_BIG; row_l[tid] = 0.f; }

    const int tr = (tid >> 4) * 4;
    const int tc = (tid & 15) * 4;
    ull acc2[4][2];   // [row][col-pair]; lo = col tc+2*j2
#pragma unroll
    for (int i = 0; i < 4; i++)
#pragma unroll
        for (int j = 0; j < 2; j++) acc2[i][j] = 0ull;

    const int kt0 = is_global ? 0 : max(0, qt - 2);
    const int kt1 = is_global ? 31 : min(31, qt + 2);

    for (int kt = kt0; kt <= kt1; kt++) {
        __syncthreads();  // prior P/V consumers done; Q/stat init done (iter 0)
        {   // load K (transposed) and V tiles
            int r = tid >> 2;
            int part = tid & 3;
            const float* ksrc = qkv + (size_t)(b * NS + kt * 64 + r) * NQKV + ND + hh * NHD + part * 16;
#pragma unroll
            for (int v = 0; v < 4; v++) {
                int d0 = part * 16 + v * 4;
                float4 k4 = *(const float4*)(ksrc + v * 4);
                Ks[(d0 + 0) * PAD + r] = k4.x;
                Ks[(d0 + 1) * PAD + r] = k4.y;
                Ks[(d0 + 2) * PAD + r] = k4.z;
                Ks[(d0 + 3) * PAD + r] = k4.w;
                *(float4*)&Vs[r * PAD + d0] = *(const float4*)(ksrc + ND + v * 4);
            }
        }
        __syncthreads();

        // S = Q K^T : 4 rows x 2 col-pairs per thread, FFMA2
        ull sv2[4][2];
#pragma unroll
        for (int i = 0; i < 4; i++)
#pragma unroll
            for (int j = 0; j < 2; j++) sv2[i][j] = 0ull;
#pragma unroll 8
        for (int d = 0; d < 64; d++) {
            float qa[4];
            *(float4*)qa = *(const float4*)&Qt[d * PAD + tr];
            ull kb0 = *(const ull*)&Ks[d * PAD + tc];
            ull kb1 = *(const ull*)&Ks[d * PAD + tc + 2];
#pragma unroll
            for (int i = 0; i < 4; i++) {
                ull qd = f2_dup(qa[i]);
                f2_fma(sv2[i][0], qd, kb0);
                f2_fma(sv2[i][1], qd, kb1);
            }
        }
        float sv[4][4];
#pragma unroll
        for (int i = 0; i < 4; i++) {
            f2_unpack(sv2[i][0], sv[i][0], sv[i][1]);
            f2_unpack(sv2[i][1], sv[i][2], sv[i][3]);
        }
        if (!is_global) {
#pragma unroll
            for (int i = 0; i < 4; i++)
#pragma unroll
                for (int j = 0; j < 4; j++) {
                    int dlt = (q0 + tr + i) - (kt * 64 + tc + j);
                    if (dlt < 0) dlt = -dlt;
                    if (dlt > 128) sv[i][j] = NEG_BIG;
                }
        }
        __syncthreads();  // K fully consumed -> reuse buffer for P
#pragma unroll
        for (int i = 0; i < 4; i++)
#pragma unroll
            for (int j = 0; j < 4; j++)
                Ks[(tr + i) * PAD + tc + j] = sv[i][j];
        __syncthreads();

        // Online softmax update: 4 lanes per row, 16 entries each
        {
            int r  = tid >> 2;
            int qd = tid & 3;
            float* Pr = &Ks[r * PAD + qd * 16];
            float mloc = NEG_BIG;
#pragma unroll
            for (int c = 0; c < 16; c++) mloc = fmaxf(mloc, Pr[c]);
            mloc = fmaxf(mloc, __shfl_xor_sync(0xffffffffu, mloc, 1));
            mloc = fmaxf(mloc, __shfl_xor_sync(0xffffffffu, mloc, 2));
            float m_old = row_m[r];
            float m_new = fmaxf(m_old, mloc);
            float ls = 0.f;
#pragma unroll
            for (int c = 0; c < 16; c++) {
                float e = __expf(Pr[c] - m_new);
                Pr[c] = e;
                ls += e;
            }
            ls += __shfl_xor_sync(0xffffffffu, ls, 1);
            ls += __shfl_xor_sync(0xffffffffu, ls, 2);
            if (qd == 0) {
                float fac = __expf(m_old - m_new);   // 0 on first tile
                row_s[r] = fac;
                row_m[r] = m_new;
                row_l[r] = row_l[r] * fac + ls;
            }
        }
        __syncthreads();

        // Rescale accumulator (packed), then O += P @ V (FFMA2)
        {
#pragma unroll
            for (int i = 0; i < 4; i++) {
                ull fd = f2_dup(row_s[tr + i]);
                acc2[i][0] = f2_mul(acc2[i][0], fd);
                acc2[i][1] = f2_mul(acc2[i][1], fd);
            }
#pragma unroll 8
            for (int c = 0; c < 64; c++) {
                ull vv0 = *(const ull*)&Vs[c * PAD + tc];
                ull vv1 = *(const ull*)&Vs[c * PAD + tc + 2];
#pragma unroll
                for (int i = 0; i < 4; i++) {
                    ull pd = f2_dup(Ks[(tr + i) * PAD + c]);
                    f2_fma(acc2[i][0], pd, vv0);
                    f2_fma(acc2[i][1], pd, vv1);
                }
            }
        }
    }

    // Normalize and write out [b*NS+s][h*64+d]
#pragma unroll
    for (int i = 0; i < 4; i++) {
        float inv = 1.f / row_l[tr + i];
        float o[4];
        f2_unpack(acc2[i][0], o[0], o[1]);
        f2_unpack(acc2[i][1], o[2], o[3]);
        float4 ov = make_float4(o[0] * inv, o[1] * inv, o[2] * inv, o[3] * inv);
        *(float4*)&aout[(size_t)(b * NS + q0 + tr + i) * ND + hh * NHD + tc] = ov;
    }
}

// ---------------------------------------------------------------------------
extern "C" void kernel_launch(void* const* d_in, const int* in_sizes, int n_in,
                              void* d_out, int out_size)
{
    const float* x     = (const float*)d_in[0];
    const float* Wqkv  = (const float*)d_in[1];
    const float* bqkv  = (const float*)d_in[2];
    const float* Wout  = (const float*)d_in[3];
    const float* bout  = (const float*)d_in[4];
    const int*   layer = (const int*)d_in[5];
    float* out = (float*)d_out;

    float *qkv, *attn;
    cudaGetSymbolAddress((void**)&qkv,  g_qkv);
    cudaGetSymbolAddress((void**)&attn, g_attn);

    const int attn_smem = (3 * 64 * PAD + 3 * 64) * (int)sizeof(float);  // 52992 B
    cudaFuncSetAttribute(attn_kernel, cudaFuncAttributeMaxDynamicSharedMemorySize, attn_smem);

    // 1) qkv = x @ Wqkv + bqkv
    sgemm_bias_kernel<<<dim3(NQKV / 128, NROWS / 128), 256>>>(x, Wqkv, bqkv, qkv,
                                                              NROWS, NQKV, ND);
    // 2) RoPE in-place on q,k
    rope_kernel<<<(NROWS * NH * 32) / 256, 256>>>(qkv, layer);
    // 3) banded attention
    attn_kernel<<<NB * NH * 32, 256, attn_smem>>>(qkv, attn, layer);
    // 4) out = attn @ Wout + bout
    sgemm_bias_kernel<<<dim3(ND / 128, NROWS / 128), 256>>>(attn, Wout, bout, out,
                                                            NROWS, ND, ND);
}

// round 7
// speedup vs baseline: 1.7008x; 1.7008x over previous
#include <cuda_runtime.h>
#include <cuda_bf16.h>
#include <math.h>
#include <stdint.h>

#define NB 2
#define NS 2048
#define ND 768
#define NH 12
#define NHD 64
#define NQKV 2304
#define NROWS 4096   // NB*NS

#define NEG_BIG (-1e30f)
#define PAD 68

// ---------------- scratch (device globals; allocation-free) -----------------
__device__ float g_qkv[(size_t)NROWS * NQKV];                 // 37.7 MB
__device__ float g_attn[(size_t)NROWS * ND];                  // 12.6 MB
__device__ __nv_bfloat16 g_xh[(size_t)NROWS * ND];            // x hi
__device__ __nv_bfloat16 g_xl[(size_t)NROWS * ND];            // x lo
__device__ __nv_bfloat16 g_ah[(size_t)NROWS * ND];            // attn hi
__device__ __nv_bfloat16 g_al[(size_t)NROWS * ND];            // attn lo
__device__ __nv_bfloat16 g_wqh[(size_t)NQKV * ND];            // Wqkv^T hi [N][K]
__device__ __nv_bfloat16 g_wql[(size_t)NQKV * ND];
__device__ __nv_bfloat16 g_woh[(size_t)ND * ND];              // Wout^T hi [N][K]
__device__ __nv_bfloat16 g_wol[(size_t)ND * ND];

__device__ __forceinline__ uint32_t smem_u32(const void* p) {
    uint32_t a;
    asm("{ .reg .u64 t; cvta.to.shared.u64 t, %1; cvt.u32.u64 %0, t; }" : "=r"(a) : "l"(p));
    return a;
}

__device__ __forceinline__ void mma_bf16(float c[4], const uint32_t a[4], const uint32_t b[2]) {
    asm volatile(
        "mma.sync.aligned.m16n8k16.row.col.f32.bf16.bf16.f32 "
        "{%0,%1,%2,%3}, {%4,%5,%6,%7}, {%8,%9}, {%0,%1,%2,%3};"
        : "+f"(c[0]), "+f"(c[1]), "+f"(c[2]), "+f"(c[3])
        : "r"(a[0]), "r"(a[1]), "r"(a[2]), "r"(a[3]), "r"(b[0]), "r"(b[1]));
}

#define LDSM4(r, addr) \
    asm volatile("ldmatrix.sync.aligned.m8n8.x4.shared.b16 {%0,%1,%2,%3}, [%4];" \
                 : "=r"((r)[0]), "=r"((r)[1]), "=r"((r)[2]), "=r"((r)[3]) : "r"(addr))

// ---------------------------------------------------------------------------
// Convert fp32 row-major [R][C] -> bf16 hi/lo planes (same layout).
// ---------------------------------------------------------------------------
__global__ void conv_rows_kernel(const float* __restrict__ in,
                                 __nv_bfloat16* __restrict__ oh,
                                 __nv_bfloat16* __restrict__ ol, int n2)
{
    int i = blockIdx.x * blockDim.x + threadIdx.x;
    if (i >= n2) return;
    float2 v = ((const float2*)in)[i];
    __nv_bfloat16 h0 = __float2bfloat16_rn(v.x);
    __nv_bfloat16 h1 = __float2bfloat16_rn(v.y);
    __nv_bfloat16 l0 = __float2bfloat16_rn(v.x - __bfloat162float(h0));
    __nv_bfloat16 l1 = __float2bfloat16_rn(v.y - __bfloat162float(h1));
    ((__nv_bfloat162*)oh)[i] = __nv_bfloat162(h0, h1);
    ((__nv_bfloat162*)ol)[i] = __nv_bfloat162(l0, l1);
}

// ---------------------------------------------------------------------------
// Transpose-convert: W fp32 [K][N] -> out bf16 [N][K] hi/lo planes.
// grid (N/32, K/32), block (32, 8).
// ---------------------------------------------------------------------------
__global__ void convT_kernel(const float* __restrict__ W,
                             __nv_bfloat16* __restrict__ oh,
                             __nv_bfloat16* __restrict__ ol, int K, int N)
{
    __shared__ float t[32][33];
    const int n0 = blockIdx.x * 32, k0 = blockIdx.y * 32;
#pragma unroll
    for (int i = 0; i < 4; i++) {
        int k = threadIdx.y + i * 8;
        t[k][threadIdx.x] = W[(size_t)(k0 + k) * N + n0 + threadIdx.x];
    }
    __syncthreads();
#pragma unroll
    for (int i = 0; i < 4; i++) {
        int n = threadIdx.y + i * 8;
        float x = t[threadIdx.x][n];
        __nv_bfloat16 h = __float2bfloat16_rn(x);
        __nv_bfloat16 l = __float2bfloat16_rn(x - __bfloat162float(h));
        size_t o = (size_t)(n0 + n) * K + k0 + threadIdx.x;
        oh[o] = h;
        ol[o] = l;
    }
}

// ---------------------------------------------------------------------------
// Tensor-core GEMM + bias via mma.sync (bf16x3 split):
//   C[M,N] = Ah@Bh^T + Ah@Bl^T + Al@Bh^T + bias      (fp32 accum/output)
// A planes: [M][K] bf16, B planes: [N][K] bf16 (pre-transposed weights).
// Block 128x128, BK=64, 8 warps, warp tile 64x32 (4 m16 x 4 n8).
// Smem rows padded to 72 bf16 (144 B) -> conflict-free ldmatrix.
// ---------------------------------------------------------------------------
#define SROW 144            // bytes per smem row (72 bf16)
#define PLANE (128 * SROW)  // 18432 B

__global__ __launch_bounds__(256)
void gemm_mma_kernel(const __nv_bfloat16* __restrict__ Ah, const __nv_bfloat16* __restrict__ Al,
                     const __nv_bfloat16* __restrict__ Bh, const __nv_bfloat16* __restrict__ Bl,
                     const float* __restrict__ bias, float* __restrict__ C,
                     int M, int N, int K)
{
    extern __shared__ __align__(16) char sm[];
    char* sAh = sm;
    char* sAl = sm + PLANE;
    char* sBh = sm + 2 * PLANE;
    char* sBl = sm + 3 * PLANE;

    const int tid = threadIdx.x;
    const int w   = tid >> 5;
    const int l   = tid & 31;
    const int row0 = blockIdx.y * 128;
    const int col0 = blockIdx.x * 128;
    const int m0w = (w >> 2) * 64;   // warp M origin in tile
    const int n0w = (w & 3) * 32;    // warp N origin in tile

    float acc[4][4][4];
#pragma unroll
    for (int i = 0; i < 4; i++)
#pragma unroll
        for (int j = 0; j < 4; j++)
#pragma unroll
            for (int q = 0; q < 4; q++) acc[i][j][q] = 0.f;

    const uint32_t sb = smem_u32(sm);
    // A ldmatrix lane address: m = m0w + 16*mt + (l&15), k = ks + ((l>>4)<<3)
    const uint32_t aOffH = sb + (uint32_t)(m0w + (l & 15)) * SROW + (uint32_t)(((l >> 4) << 3) * 2);
    const uint32_t aOffL = aOffH + PLANE;
    // B ldmatrix lane address (two n8 tiles per x4): g=l>>3, kh=g&1, tl=g>>1
    const int bg = l >> 3;
    const uint32_t bOffH = sb + 2 * PLANE
        + (uint32_t)(n0w + (bg >> 1) * 8 + (l & 7)) * SROW + (uint32_t)(((bg & 1) * 8) * 2);
    const uint32_t bOffL = bOffH + PLANE;

    const int fr = tid >> 1;       // fill row 0..127
    const int fh = tid & 1;        // fill half (64B)
    const __nv_bfloat16* gAh = Ah + (size_t)(row0 + fr) * K + fh * 32;
    const __nv_bfloat16* gAl = Al + (size_t)(row0 + fr) * K + fh * 32;
    const __nv_bfloat16* gBh = Bh + (size_t)(col0 + fr) * K + fh * 32;
    const __nv_bfloat16* gBl = Bl + (size_t)(col0 + fr) * K + fh * 32;
    uint4* stA_h = (uint4*)(sAh + fr * SROW + fh * 64);
    uint4* stA_l = (uint4*)(sAl + fr * SROW + fh * 64);
    uint4* stB_h = (uint4*)(sBh + fr * SROW + fh * 64);
    uint4* stB_l = (uint4*)(sBl + fr * SROW + fh * 64);

    const int nchunks = K >> 6;
    for (int kc = 0; kc < nchunks; kc++) {
        const int ke = kc << 6;   // element offset
        {
            const uint4* p;
            p = (const uint4*)(gAh + ke);
#pragma unroll
            for (int i = 0; i < 4; i++) stA_h[i] = p[i];
            p = (const uint4*)(gAl + ke);
#pragma unroll
            for (int i = 0; i < 4; i++) stA_l[i] = p[i];
            p = (const uint4*)(gBh + ke);
#pragma unroll
            for (int i = 0; i < 4; i++) stB_h[i] = p[i];
            p = (const uint4*)(gBl + ke);
#pragma unroll
            for (int i = 0; i < 4; i++) stB_l[i] = p[i];
        }
        __syncthreads();

#pragma unroll
        for (int s = 0; s < 4; s++) {
            const uint32_t kso = (uint32_t)(s * 32);   // 16 bf16 = 32 B
            uint32_t ah[4][4], al[4][4];
#pragma unroll
            for (int mt = 0; mt < 4; mt++) {
                LDSM4(ah[mt], aOffH + mt * (16 * SROW) + kso);
                LDSM4(al[mt], aOffL + mt * (16 * SROW) + kso);
            }
            uint32_t bh[4][2], bl[4][2];
#pragma unroll
            for (int jp = 0; jp < 2; jp++) {
                uint32_t r[4];
                LDSM4(r, bOffH + jp * (16 * SROW) + kso);
                bh[2 * jp][0] = r[0]; bh[2 * jp][1] = r[1];
                bh[2 * jp + 1][0] = r[2]; bh[2 * jp + 1][1] = r[3];
                LDSM4(r, bOffL + jp * (16 * SROW) + kso);
                bl[2 * jp][0] = r[0]; bl[2 * jp][1] = r[1];
                bl[2 * jp + 1][0] = r[2]; bl[2 * jp + 1][1] = r[3];
            }
#pragma unroll
            for (int mt = 0; mt < 4; mt++)
#pragma unroll
                for (int nt = 0; nt < 4; nt++)
                    mma_bf16(acc[mt][nt], ah[mt], bh[nt]);
#pragma unroll
            for (int mt = 0; mt < 4; mt++)
#pragma unroll
                for (int nt = 0; nt < 4; nt++)
                    mma_bf16(acc[mt][nt], ah[mt], bl[nt]);
#pragma unroll
            for (int mt = 0; mt < 4; mt++)
#pragma unroll
                for (int nt = 0; nt < 4; nt++)
                    mma_bf16(acc[mt][nt], al[mt], bh[nt]);
        }
        __syncthreads();
    }

    // epilogue: bias + direct stores (float2, frag layout)
    float2 bb[4];
#pragma unroll
    for (int nt = 0; nt < 4; nt++) {
        int cg = col0 + n0w + 8 * nt + 2 * (l & 3);
        bb[nt] = make_float2(bias[cg], bias[cg + 1]);
    }
#pragma unroll
    for (int mt = 0; mt < 4; mt++) {
        int rg = row0 + m0w + 16 * mt + (l >> 2);
#pragma unroll
        for (int nt = 0; nt < 4; nt++) {
            int cg = col0 + n0w + 8 * nt + 2 * (l & 3);
            *(float2*)&C[(size_t)rg * N + cg] =
                make_float2(acc[mt][nt][0] + bb[nt].x, acc[mt][nt][1] + bb[nt].y);
            *(float2*)&C[(size_t)(rg + 8) * N + cg] =
                make_float2(acc[mt][nt][2] + bb[nt].x, acc[mt][nt][3] + bb[nt].y);
        }
    }
}

// ---------------------------------------------------------------------------
// RoPE in-place on q and k parts of qkv. One thread per (b,s,h,pair).
// ---------------------------------------------------------------------------
__global__ void rope_kernel(float* __restrict__ qkv, const int* __restrict__ layer_p)
{
    int idx = blockIdx.x * blockDim.x + threadIdx.x;
    if (idx >= NROWS * NH * 32) return;
    int i  = idx & 31;
    int hh = (idx >> 5) % NH;
    int bs = (idx >> 5) / NH;
    int s  = bs & (NS - 1);

    bool is_global = (layer_p[0] % 3) == 0;
    float theta = is_global ? 160000.f : 10000.f;
    float freq  = powf(theta, -(float)(2 * i) / 64.f);
    float ang   = (float)s * freq;
    float sn, cs;
    sincosf(ang, &sn, &cs);

    size_t base = (size_t)bs * NQKV + hh * NHD + 2 * i;
    float qe = qkv[base], qo = qkv[base + 1];
    qkv[base]      = qe * cs - qo * sn;
    qkv[base + 1]  = qo * cs + qe * sn;
    float ke = qkv[base + ND], ko = qkv[base + ND + 1];
    qkv[base + ND]     = ke * cs - ko * sn;
    qkv[base + ND + 1] = ko * cs + ke * sn;
}

// ---------------------------------------------------------------------------
// Flash-style banded attention (round-1 version).
// ---------------------------------------------------------------------------
__global__ __launch_bounds__(256, 1)
void attn_kernel(const float* __restrict__ qkv, float* __restrict__ aout,
                 const int* __restrict__ layer_p)
{
    extern __shared__ float smf[];
    float* Qt    = smf;
    float* Ks    = Qt + 64 * PAD;
    float* Vs    = Ks + 64 * PAD;
    float* row_m = Vs + 64 * PAD;
    float* row_l = row_m + 64;
    float* row_s = row_l + 64;

    const int tid = threadIdx.x;
    const int blk = blockIdx.x;
    const int qt  = blk & 31;
    const int hh  = (blk >> 5) % NH;
    const int b   = blk / (32 * NH);
    const bool is_global = (layer_p[0] % 3) == 0;
    const int q0 = qt * 64;

    {
        int r = tid >> 2;
        int part = tid & 3;
        const float* src = qkv + (size_t)(b * NS + q0 + r) * NQKV + hh * NHD + part * 16;
#pragma unroll
        for (int v = 0; v < 4; v++) {
            float4 q4 = *(const float4*)(src + v * 4);
            int d0 = part * 16 + v * 4;
            Qt[(d0 + 0) * PAD + r] = q4.x * 0.125f;
            Qt[(d0 + 1) * PAD + r] = q4.y * 0.125f;
            Qt[(d0 + 2) * PAD + r] = q4.z * 0.125f;
            Qt[(d0 + 3) * PAD + r] = q4.w * 0.125f;
        }
    }
    if (tid < 64) { row_m[tid] = NEG_BIG; row_l[tid] = 0.f; }

    const int tr = (tid >> 4) * 4;
    const int tc = (tid & 15) * 4;
    float acc[4][4];
#pragma unroll
    for (int i = 0; i < 4; i++)
#pragma unroll
        for (int j = 0; j < 4; j++) acc[i][j] = 0.f;

    const int kt0 = is_global ? 0 : max(0, qt - 2);
    const int kt1 = is_global ? 31 : min(31, qt + 2);

    for (int kt = kt0; kt <= kt1; kt++) {
        __syncthreads();
        {
            int r = tid >> 2;
            int part = tid & 3;
            const float* ksrc = qkv + (size_t)(b * NS + kt * 64 + r) * NQKV + ND + hh * NHD + part * 16;
#pragma unroll
            for (int v = 0; v < 4; v++) {
                int d0 = part * 16 + v * 4;
                float4 k4 = *(const float4*)(ksrc + v * 4);
                Ks[(d0 + 0) * PAD + r] = k4.x;
                Ks[(d0 + 1) * PAD + r] = k4.y;
                Ks[(d0 + 2) * PAD + r] = k4.z;
                Ks[(d0 + 3) * PAD + r] = k4.w;
                *(float4*)&Vs[r * PAD + d0] = *(const float4*)(ksrc + ND + v * 4);
            }
        }
        __syncthreads();

        float sv[4][4];
#pragma unroll
        for (int i = 0; i < 4; i++)
#pragma unroll
            for (int j = 0; j < 4; j++) sv[i][j] = 0.f;
#pragma unroll 8
        for (int d = 0; d < 64; d++) {
            float qa[4], kb[4];
            *(float4*)qa = *(const float4*)&Qt[d * PAD + tr];
            *(float4*)kb = *(const float4*)&Ks[d * PAD + tc];
#pragma unroll
            for (int i = 0; i < 4; i++)
#pragma unroll
                for (int j = 0; j < 4; j++)
                    sv[i][j] = fmaf(qa[i], kb[j], sv[i][j]);
        }
        if (!is_global) {
#pragma unroll
            for (int i = 0; i < 4; i++)
#pragma unroll
                for (int j = 0; j < 4; j++) {
                    int dlt = (q0 + tr + i) - (kt * 64 + tc + j);
                    if (dlt < 0) dlt = -dlt;
                    if (dlt > 128) sv[i][j] = NEG_BIG;
                }
        }
        __syncthreads();
#pragma unroll
        for (int i = 0; i < 4; i++)
#pragma unroll
            for (int j = 0; j < 4; j++)
                Ks[(tr + i) * PAD + tc + j] = sv[i][j];
        __syncthreads();

        {
            int r  = tid >> 2;
            int qd = tid & 3;
            float* Pr = &Ks[r * PAD + qd * 16];
            float mloc = NEG_BIG;
#pragma unroll
            for (int c = 0; c < 16; c++) mloc = fmaxf(mloc, Pr[c]);
            mloc = fmaxf(mloc, __shfl_xor_sync(0xffffffffu, mloc, 1));
            mloc = fmaxf(mloc, __shfl_xor_sync(0xffffffffu, mloc, 2));
            float m_old = row_m[r];
            float m_new = fmaxf(m_old, mloc);
            float ls = 0.f;
#pragma unroll
            for (int c = 0; c < 16; c++) {
                float e = expf(Pr[c] - m_new);
                Pr[c] = e;
                ls += e;
            }
            ls += __shfl_xor_sync(0xffffffffu, ls, 1);
            ls += __shfl_xor_sync(0xffffffffu, ls, 2);
            if (qd == 0) {
                float fac = expf(m_old - m_new);
                row_s[r] = fac;
                row_m[r] = m_new;
                row_l[r] = row_l[r] * fac + ls;
            }
        }
        __syncthreads();

        {
            float fac[4];
#pragma unroll
            for (int i = 0; i < 4; i++) fac[i] = row_s[tr + i];
#pragma unroll
            for (int i = 0; i < 4; i++)
#pragma unroll
                for (int j = 0; j < 4; j++) acc[i][j] *= fac[i];
#pragma unroll 8
            for (int c = 0; c < 64; c++) {
                float vv[4], pp[4];
                *(float4*)vv = *(const float4*)&Vs[c * PAD + tc];
#pragma unroll
                for (int i = 0; i < 4; i++) pp[i] = Ks[(tr + i) * PAD + c];
#pragma unroll
                for (int i = 0; i < 4; i++)
#pragma unroll
                    for (int j = 0; j < 4; j++)
                        acc[i][j] = fmaf(pp[i], vv[j], acc[i][j]);
            }
        }
    }

#pragma unroll
    for (int i = 0; i < 4; i++) {
        float inv = 1.f / row_l[tr + i];
        float4 o = make_float4(acc[i][0] * inv, acc[i][1] * inv,
                               acc[i][2] * inv, acc[i][3] * inv);
        *(float4*)&aout[(size_t)(b * NS + q0 + tr + i) * ND + hh * NHD + tc] = o;
    }
}

// ---------------------------------------------------------------------------
extern "C" void kernel_launch(void* const* d_in, const int* in_sizes, int n_in,
                              void* d_out, int out_size)
{
    const float* x     = (const float*)d_in[0];
    const float* Wqkv  = (const float*)d_in[1];
    const float* bqkv  = (const float*)d_in[2];
    const float* Wout  = (const float*)d_in[3];
    const float* bout  = (const float*)d_in[4];
    const int*   layer = (const int*)d_in[5];
    float* out = (float*)d_out;

    float *qkv, *attn;
    __nv_bfloat16 *xh, *xl, *ah, *al, *wqh, *wql, *woh, *wol;
    cudaGetSymbolAddress((void**)&qkv,  g_qkv);
    cudaGetSymbolAddress((void**)&attn, g_attn);
    cudaGetSymbolAddress((void**)&xh, g_xh);
    cudaGetSymbolAddress((void**)&xl, g_xl);
    cudaGetSymbolAddress((void**)&ah, g_ah);
    cudaGetSymbolAddress((void**)&al, g_al);
    cudaGetSymbolAddress((void**)&wqh, g_wqh);
    cudaGetSymbolAddress((void**)&wql, g_wql);
    cudaGetSymbolAddress((void**)&woh, g_woh);
    cudaGetSymbolAddress((void**)&wol, g_wol);

    const int gemm_smem = 4 * PLANE;   // 73728 B
    cudaFuncSetAttribute(gemm_mma_kernel, cudaFuncAttributeMaxDynamicSharedMemorySize, gemm_smem);
    const int attn_smem = (3 * 64 * PAD + 3 * 64) * (int)sizeof(float);  // 52992 B
    cudaFuncSetAttribute(attn_kernel, cudaFuncAttributeMaxDynamicSharedMemorySize, attn_smem);

    // 0) conversions
    conv_rows_kernel<<<(NROWS * ND / 2 + 255) / 256, 256>>>(x, xh, xl, NROWS * ND / 2);
    convT_kernel<<<dim3(NQKV / 32, ND / 32), dim3(32, 8)>>>(Wqkv, wqh, wql, ND, NQKV);
    convT_kernel<<<dim3(ND / 32, ND / 32), dim3(32, 8)>>>(Wout, woh, wol, ND, ND);

    // 1) qkv = x @ Wqkv + bqkv   (mma.sync tensor cores)
    gemm_mma_kernel<<<dim3(NQKV / 128, NROWS / 128), 256, gemm_smem>>>(
        xh, xl, wqh, wql, bqkv, qkv, NROWS, NQKV, ND);
    // 2) RoPE in-place on q,k
    rope_kernel<<<(NROWS * NH * 32) / 256, 256>>>(qkv, layer);
    // 3) banded attention
    attn_kernel<<<NB * NH * 32, 256, attn_smem>>>(qkv, attn, layer);
    // 4) convert attn, then out = attn @ Wout + bout
    conv_rows_kernel<<<(NROWS * ND / 2 + 255) / 256, 256>>>(attn, ah, al, NROWS * ND / 2);
    gemm_mma_kernel<<<dim3(ND / 128, NROWS / 128), 256, gemm_smem>>>(
        ah, al, woh, wol, bout, out, NROWS, ND, ND);
}